// round 10
// baseline (speedup 1.0000x reference)
#include <cuda_runtime.h>
#include <cstdint>

// 2-bit quantized embedding gather — R10: decode into SMEM, TMA bulk store.
// input_ids: [262144] int32 ; bit_arr: [3.2M] int32 ; codebook: [4] fp32
// out: [262144, 128] fp32.
//
// R9 post-mortem: MLP scaling exhausted (TOK=16 neutral). New theory: the
// per-token STG.128 (12-cyc LSU issue + 4 L1 wavefronts each) is the wall.
// This version: each block decodes 64 consecutive tokens (8 per warp, the
// R8-best MLP) into a 32KB SMEM tile via STS.128, then ONE
// cp.async.bulk.global.shared::cta moves the contiguous 32KB to GMEM via
// the TMA engine — no STG instructions, no L1 store wavefronts.

#define TOK_PER_WARP   8
#define WARPS_PER_BLK  8
#define TOK_PER_BLK    (TOK_PER_WARP * WARPS_PER_BLK)   // 64 tokens = 32 KB out

__global__ __launch_bounds__(256)
void embed2bit_kernel(const int4* __restrict__ ids4,
                      const unsigned int* __restrict__ bits,
                      const float* __restrict__ cb,
                      float4* __restrict__ out,
                      int n_tokens)
{
    __shared__ float4 stage[TOK_PER_BLK * 32];   // 64 tokens x 512 B = 32 KB

    int wid  = threadIdx.x >> 5;
    int lane = threadIdx.x & 31;
    int blk_tok = blockIdx.x * TOK_PER_BLK;
    int tok_base = blk_tok + wid * TOK_PER_WARP;
    if (tok_base >= n_tokens) return;

    int gwarp = blockIdx.x * WARPS_PER_BLK + wid;

    // Two independent warp-uniform 16B loads = 8 token ids.
    int4 ta = __ldg(&ids4[gwarp * 2 + 0]);
    int4 tb = __ldg(&ids4[gwarp * 2 + 1]);
    unsigned int tok[TOK_PER_WARP] = {
        (unsigned int)ta.x, (unsigned int)ta.y,
        (unsigned int)ta.z, (unsigned int)ta.w,
        (unsigned int)tb.x, (unsigned int)tb.y,
        (unsigned int)tb.z, (unsigned int)tb.w };

    // 8 independent code-block loads in flight (MLP=8). 4 lanes share a word.
    unsigned int w[TOK_PER_WARP];
    #pragma unroll
    for (int j = 0; j < TOK_PER_WARP; j++)
        w[j] = __ldg(&bits[(size_t)tok[j] * 8 + (lane >> 2)]);

    // Codebook in registers; decode via predicated selects, no memory LUT.
    float c0 = __ldg(&cb[0]);
    float c1 = __ldg(&cb[1]);
    float c2 = __ldg(&cb[2]);
    float c3 = __ldg(&cb[3]);

    #define DECODE(c) (((c) & 1u) ? (((c) & 2u) ? c3 : c1) \
                                  : (((c) & 2u) ? c2 : c0))
    unsigned int sel = lane & 3;
    float4* sbase = &stage[(wid * TOK_PER_WARP) * 32 + lane];

    #pragma unroll
    for (int j = 0; j < TOK_PER_WARP; j++) {
        unsigned int byte = __byte_perm(w[j], 0u, sel) & 0xFFu;  // 1 PRMT
        float4 v;
        v.x = DECODE(((byte >> 0) & 3u));
        v.y = DECODE(((byte >> 2) & 3u));
        v.z = DECODE(((byte >> 4) & 3u));
        v.w = DECODE(((byte >> 6) & 3u));
        sbase[j * 32] = v;   // STS.128, 512 B contiguous per warp, conflict-free
    }
    #undef DECODE

    __syncthreads();

    // One TMA bulk store: 32 KB contiguous SMEM -> GMEM (output is contiguous
    // because tokens are processed in order).
    if (threadIdx.x == 0) {
        asm volatile("fence.proxy.async.shared::cta;" ::: "memory");
        uint32_t saddr;
        asm("{ .reg .u64 t; cvta.to.shared.u64 t, %1; cvt.u32.u64 %0, t; }"
            : "=r"(saddr) : "l"(stage));
        const float4* gdst = out + (size_t)blk_tok * 32;
        asm volatile(
            "cp.async.bulk.global.shared::cta.bulk_group [%0], [%1], %2;"
            :: "l"(gdst), "r"(saddr), "r"((unsigned)(TOK_PER_BLK * 512))
            : "memory");
        asm volatile("cp.async.bulk.commit_group;" ::: "memory");
        asm volatile("cp.async.bulk.wait_group 0;" ::: "memory");
    }
}

extern "C" void kernel_launch(void* const* d_in, const int* in_sizes, int n_in,
                              void* d_out, int out_size)
{
    const int4*         ids4 = (const int4*)d_in[0];
    const unsigned int* bits = (const unsigned int*)d_in[1];
    const float*        cb   = (const float*)d_in[2];
    float4*             out  = (float4*)d_out;

    int n_tokens = in_sizes[0];                       // 262144 (divisible by 64)
    int blocks = (n_tokens + TOK_PER_BLK - 1) / TOK_PER_BLK;   // 4096

    embed2bit_kernel<<<blocks, 256>>>(ids4, bits, cb, out, n_tokens);
}